// round 11
// baseline (speedup 1.0000x reference)
#include <cuda_runtime.h>
#include <math.h>
#include <stdint.h>

#define B_ 4
#define S_ 2048
#define DM 512
#define H_ 8

// ---------------- scratch (device globals; no runtime alloc) ----------------
__device__ uint32_t g_bh[(size_t)8192*256], g_bl[(size_t)8192*256];   // LN out hi/lo (bf16 pairs)
__device__ uint32_t g_qh[(size_t)8192*256], g_ql[(size_t)8192*256];
__device__ uint32_t g_kh[(size_t)8192*256], g_kl[(size_t)8192*256];
__device__ uint32_t g_vh[(size_t)8192*256], g_vl[(size_t)8192*256];
__device__ uint32_t g_wh[4*131072], g_wl[4*131072];                   // 4 pre-split W
__device__ float    g_oh[(size_t)8192*512];                           // attn out (f32)

// ---------------- bf16 helpers ----------------
__device__ __forceinline__ uint32_t pack_bf16(float even, float odd) {
    uint32_t r;
    asm("cvt.rn.bf16x2.f32 %0, %1, %2;" : "=r"(r) : "f"(odd), "f"(even));
    return r;
}
__device__ __forceinline__ void split2(float x0, float x1, uint32_t& hp, uint32_t& lp) {
    hp = pack_bf16(x0, x1);
    float h0 = __uint_as_float(hp << 16);
    float h1 = __uint_as_float(hp & 0xFFFF0000u);
    lp = pack_bf16(x0 - h0, x1 - h1);
}
__device__ __forceinline__ uint32_t prmt(uint32_t a, uint32_t b, uint32_t s) {
    uint32_t d;
    asm("prmt.b32 %0,%1,%2,%3;" : "=r"(d) : "r"(a), "r"(b), "r"(s));
    return d;
}
__device__ __forceinline__ void mma16(float* c, uint4 a, uint32_t b0, uint32_t b1) {
    asm("mma.sync.aligned.m16n8k16.row.col.f32.bf16.bf16.f32 "
        "{%0,%1,%2,%3}, {%4,%5,%6,%7}, {%8,%9}, {%0,%1,%2,%3};"
        : "+f"(c[0]), "+f"(c[1]), "+f"(c[2]), "+f"(c[3])
        : "r"(a.x), "r"(a.y), "r"(a.z), "r"(a.w), "r"(b0), "r"(b1));
}

// ---------------- fragment-order smem layout (g-stride 20: bank-safe) ----------------
#define A_SZ 2560              // 2 kc * 8 mt * (8 g * 20)
#define B_SZ 1280              // 2 kc * 4 nt * 160
#define BUF_SZ (2*A_SZ + 2*B_SZ)   // 7680 u32 = 30KB; x2 buffers = 60KB

__device__ __forceinline__ int ia_(int kc, int mt, int g, int t) {
    return (kc * 8 + mt) * 160 + g * 20 + t * 4;
}
__device__ __forceinline__ int ib_(int kc, int nt, int g, int t) {
    return (kc * 4 + nt) * 160 + g * 20 + t * 4;
}

// ---------------- staging: load (gmem->regs) / store (regs->smem) ----------------
// A copy-path (pre-split u32-pair arrays), 128 rows x 32k per chunk (16 u32 cols)
__device__ __forceinline__ void loadA_cp(const uint32_t* __restrict__ Hg,
                                         const uint32_t* __restrict__ Lg,
                                         int tid, uint4 rh[2], uint4 rl[2]) {
    #pragma unroll
    for (int i = 0; i < 2; i++) {
        int slot = tid + i * 256;
        int m = slot >> 2, k8 = slot & 3;
        rh[i] = *(const uint4*)&Hg[(size_t)m * 256 + k8 * 4];
        rl[i] = *(const uint4*)&Lg[(size_t)m * 256 + k8 * 4];
    }
}
__device__ __forceinline__ void storeA_cp(const uint4 rh[2], const uint4 rl[2],
                                          int tid, uint32_t* buf) {
    #pragma unroll
    for (int i = 0; i < 2; i++) {
        int slot = tid + i * 256;
        int m = slot >> 2, k8 = slot & 3;
        int kc = k8 >> 1, kh = k8 & 1, mt = m >> 4, g = m & 7, e = ((m >> 3) & 1) + 2 * kh;
        int b0 = ia_(kc, mt, g, 0) + e;
        buf[b0]          = rh[i].x;
        buf[b0 + 4]      = rh[i].y;
        buf[b0 + 8]      = rh[i].z;
        buf[b0 + 12]     = rh[i].w;
        buf[A_SZ + b0]      = rl[i].x;
        buf[A_SZ + b0 + 4]  = rl[i].y;
        buf[A_SZ + b0 + 8]  = rl[i].z;
        buf[A_SZ + b0 + 12] = rl[i].w;
    }
}
// B copy-path: 64 n x 32 k per chunk
__device__ __forceinline__ void loadB_cp(const uint32_t* __restrict__ Hg,
                                         const uint32_t* __restrict__ Lg,
                                         int tid, uint4& rh, uint4& rl) {
    int n = tid >> 2, k8 = tid & 3;
    rh = *(const uint4*)&Hg[(size_t)n * 256 + k8 * 4];
    rl = *(const uint4*)&Lg[(size_t)n * 256 + k8 * 4];
}
__device__ __forceinline__ void storeB_cp(uint4 rh, uint4 rl, int tid, uint32_t* buf) {
    int n = tid >> 2, k8 = tid & 3;
    int kc = k8 >> 1, kh = k8 & 1, nt = n >> 4, g = n & 7, e = ((n >> 3) & 1) * 2 + kh;
    uint32_t* sB = buf + 2 * A_SZ;
    int b0 = ib_(kc, nt, g, 0) + e;
    sB[b0]      = rh.x;  sB[b0 + 4]  = rh.y;  sB[b0 + 8]  = rh.z;  sB[b0 + 12] = rh.w;
    sB[B_SZ + b0]      = rl.x;  sB[B_SZ + b0 + 4]  = rl.y;
    sB[B_SZ + b0 + 8]  = rl.z;  sB[B_SZ + b0 + 12] = rl.w;
}
// A split-path (av: f32 attn -> split at stage)
__device__ __forceinline__ void loadA_sp(const float* __restrict__ Ag, size_t lda,
                                         int tid, float4 rf[4]) {
    #pragma unroll
    for (int i = 0; i < 2; i++) {
        int slot = tid + i * 256;
        int m = slot >> 2, k8 = slot & 3;
        rf[i * 2]     = *(const float4*)&Ag[(size_t)m * lda + k8 * 8];
        rf[i * 2 + 1] = *(const float4*)&Ag[(size_t)m * lda + k8 * 8 + 4];
    }
}
__device__ __forceinline__ void storeA_sp(const float4 rf[4], int tid, uint32_t* buf) {
    #pragma unroll
    for (int i = 0; i < 2; i++) {
        int slot = tid + i * 256;
        int m = slot >> 2, k8 = slot & 3;
        int kc = k8 >> 1, kh = k8 & 1, mt = m >> 4, g = m & 7, e = ((m >> 3) & 1) + 2 * kh;
        uint32_t h0, h1, h2, h3, l0, l1, l2, l3;
        split2(rf[i*2].x,   rf[i*2].y,   h0, l0);
        split2(rf[i*2].z,   rf[i*2].w,   h1, l1);
        split2(rf[i*2+1].x, rf[i*2+1].y, h2, l2);
        split2(rf[i*2+1].z, rf[i*2+1].w, h3, l3);
        int b0 = ia_(kc, mt, g, 0) + e;
        buf[b0] = h0;  buf[b0 + 4] = h1;  buf[b0 + 8] = h2;  buf[b0 + 12] = h3;
        buf[A_SZ + b0] = l0;  buf[A_SZ + b0 + 4] = l1;
        buf[A_SZ + b0 + 8] = l2;  buf[A_SZ + b0 + 12] = l3;
    }
}
// B transposed path (av V): rows = k, pre-split arrays; prmt 2x2 transpose
__device__ __forceinline__ void loadBT(const uint32_t* __restrict__ Hg,
                                       const uint32_t* __restrict__ Lg,
                                       int tid, uint32_t rh[4], uint32_t rl[4]) {
    int kq = tid >> 5, np = tid & 31;
    int kb = kq * 4;
    #pragma unroll
    for (int r = 0; r < 4; r++) {
        rh[r] = Hg[(size_t)(kb + r) * 256 + np];
        rl[r] = Lg[(size_t)(kb + r) * 256 + np];
    }
}
__device__ __forceinline__ void storeBT(const uint32_t rh[4], const uint32_t rl[4],
                                        int tid, uint32_t* buf) {
    int kq = tid >> 5, np = tid & 31;
    int kc = kq >> 2, kh = (kq >> 1) & 1, t0 = (kq & 1) * 2;
    int nt = np >> 3, g0 = (np * 2) & 7, hn = (np >> 2) & 1;
    int e = hn * 2 + kh;
    uint32_t* sB = buf + 2 * A_SZ;
    // col n0 = 2*np (low halves), col n1 = 2*np+1 (high halves)
    int x0 = ib_(kc, nt, g0, t0) + e;
    int x1 = ib_(kc, nt, g0 + 1, t0) + e;
    sB[x0]     = prmt(rh[0], rh[1], 0x5410);
    sB[x0 + 4] = prmt(rh[2], rh[3], 0x5410);
    sB[x1]     = prmt(rh[0], rh[1], 0x7632);
    sB[x1 + 4] = prmt(rh[2], rh[3], 0x7632);
    sB[B_SZ + x0]     = prmt(rl[0], rl[1], 0x5410);
    sB[B_SZ + x0 + 4] = prmt(rl[2], rl[3], 0x5410);
    sB[B_SZ + x1]     = prmt(rl[0], rl[1], 0x7632);
    sB[B_SZ + x1 + 4] = prmt(rl[2], rl[3], 0x7632);
}

// ---------------- compute: one 32-k chunk, 8 warps (4m x 2n), warp 32x32 ----------------
__device__ __forceinline__ void compute_chunk(const uint32_t* buf, int wm, int wn,
                                              int lane, float acc[2][4][4]) {
    const uint32_t* sAh = buf;
    const uint32_t* sAl = buf + A_SZ;
    const uint32_t* sBh = buf + 2 * A_SZ;
    const uint32_t* sBl = buf + 2 * A_SZ + B_SZ;
    int g = lane >> 2, t = lane & 3;
    #pragma unroll
    for (int kc = 0; kc < 2; kc++) {
        uint4 Ah[2], Al[2], Bh[2], Bl[2];
        #pragma unroll
        for (int mtl = 0; mtl < 2; mtl++) {
            int idx = ia_(kc, wm * 2 + mtl, g, t);
            Ah[mtl] = *(const uint4*)&sAh[idx];
            Al[mtl] = *(const uint4*)&sAl[idx];
        }
        #pragma unroll
        for (int p = 0; p < 2; p++) {
            int idx = ib_(kc, wn * 2 + p, g, t);
            Bh[p] = *(const uint4*)&sBh[idx];
            Bl[p] = *(const uint4*)&sBl[idx];
        }
        #pragma unroll
        for (int mtl = 0; mtl < 2; mtl++) {
            #pragma unroll
            for (int p = 0; p < 2; p++) {
                mma16(acc[mtl][p * 2],     Ah[mtl], Bh[p].x, Bh[p].y);
                mma16(acc[mtl][p * 2],     Ah[mtl], Bl[p].x, Bl[p].y);
                mma16(acc[mtl][p * 2],     Al[mtl], Bh[p].x, Bh[p].y);
                mma16(acc[mtl][p * 2 + 1], Ah[mtl], Bh[p].z, Bh[p].w);
                mma16(acc[mtl][p * 2 + 1], Ah[mtl], Bl[p].z, Bl[p].w);
                mma16(acc[mtl][p * 2 + 1], Al[mtl], Bh[p].z, Bh[p].w);
            }
        }
    }
}

// ---------------- epilogues ----------------
__device__ __forceinline__ void store_f32(float* __restrict__ Cb, size_t ldc,
                                          int wm, int wn, int lane,
                                          float acc[2][4][4], float scale) {
    int g = lane >> 2, t = lane & 3;
    #pragma unroll
    for (int mtl = 0; mtl < 2; mtl++) {
        #pragma unroll
        for (int nt = 0; nt < 4; nt++) {
            size_t row = (size_t)(wm * 32 + mtl * 16 + g);
            size_t col = (size_t)(wn * 32 + nt * 8 + t * 2);
            float2 v0 = {acc[mtl][nt][0] * scale, acc[mtl][nt][1] * scale};
            float2 v1 = {acc[mtl][nt][2] * scale, acc[mtl][nt][3] * scale};
            *(float2*)&Cb[row * ldc + col] = v0;
            *(float2*)&Cb[(row + 8) * ldc + col] = v1;
        }
    }
}
__device__ __forceinline__ void store_split(uint32_t* __restrict__ Ch,
                                            uint32_t* __restrict__ Cl,
                                            int wm, int wn, int lane,
                                            float acc[2][4][4]) {
    int g = lane >> 2, t = lane & 3;
    #pragma unroll
    for (int mtl = 0; mtl < 2; mtl++) {
        #pragma unroll
        for (int nt = 0; nt < 4; nt++) {
            size_t row = (size_t)(wm * 32 + mtl * 16 + g);
            int cu = wn * 16 + nt * 4 + t;
            uint32_t hp, lp;
            split2(acc[mtl][nt][0], acc[mtl][nt][1], hp, lp);
            Ch[row * 256 + cu] = hp;  Cl[row * 256 + cu] = lp;
            split2(acc[mtl][nt][2], acc[mtl][nt][3], hp, lp);
            Ch[(row + 8) * 256 + cu] = hp;  Cl[(row + 8) * 256 + cu] = lp;
        }
    }
}

// ---------------- proj GEMM: C[128 x 64-block] = A[128,512] @ W^T ----------------
template<int EPI>   // 0: f32 out, 1: split out
__global__ __launch_bounds__(256) void proj_mma(const uint32_t* __restrict__ Ah,
                                                const uint32_t* __restrict__ Al,
                                                const uint32_t* __restrict__ Bh,
                                                const uint32_t* __restrict__ Bl,
                                                float* __restrict__ Cf,
                                                uint32_t* __restrict__ Ch,
                                                uint32_t* __restrict__ Cl) {
    extern __shared__ uint32_t sm[];
    uint32_t* buf0 = sm;
    uint32_t* buf1 = sm + BUF_SZ;
    int tid = threadIdx.x, lane = tid & 31, wid = tid >> 5;
    int wm = wid & 3, wn = wid >> 2;
    size_t m0 = (size_t)blockIdx.y * 128, n0 = (size_t)blockIdx.x * 64;
    const uint32_t* Ahb = Ah + m0 * 256;
    const uint32_t* Alb = Al + m0 * 256;
    const uint32_t* Bhb = Bh + n0 * 256;
    const uint32_t* Blb = Bl + n0 * 256;

    uint4 rah[2], ral[2], rbh, rbl;
    float acc[2][4][4] = {};

    loadA_cp(Ahb, Alb, tid, rah, ral);
    loadB_cp(Bhb, Blb, tid, rbh, rbl);
    storeA_cp(rah, ral, tid, buf0);
    storeB_cp(rbh, rbl, tid, buf0);
    __syncthreads();

    const int NC = DM / 32;   // 16
    for (int c = 0; c < NC; c++) {
        uint32_t* cur = (c & 1) ? buf1 : buf0;
        uint32_t* nxt = (c & 1) ? buf0 : buf1;
        if (c + 1 < NC) {
            loadA_cp(Ahb + (c + 1) * 16, Alb + (c + 1) * 16, tid, rah, ral);
            loadB_cp(Bhb + (c + 1) * 16, Blb + (c + 1) * 16, tid, rbh, rbl);
        }
        compute_chunk(cur, wm, wn, lane, acc);
        if (c + 1 < NC) {
            storeA_cp(rah, ral, tid, nxt);
            storeB_cp(rbh, rbl, tid, nxt);
        }
        __syncthreads();
    }
    if (EPI == 0)
        store_f32(Cf + m0 * DM + n0, DM, wm, wn, lane, acc, 1.0f);
    else
        store_split(Ch + m0 * 256 + (n0 >> 1), Cl + m0 * 256 + (n0 >> 1), wm, wn, lane, acc);
}

// ---------------- scores: attn = 0.125 * Q @ K^T; CTA does 4 sk-tiles ----------------
__global__ __launch_bounds__(256) void scores_mma(const uint32_t* __restrict__ Qh,
                                                  const uint32_t* __restrict__ Ql,
                                                  const uint32_t* __restrict__ Kh,
                                                  const uint32_t* __restrict__ Kl,
                                                  float* __restrict__ attn) {
    extern __shared__ uint32_t sm[];
    uint32_t* buf0 = sm;
    uint32_t* buf1 = sm + BUF_SZ;
    int tid = threadIdx.x, lane = tid & 31, wid = tid >> 5;
    int wm = wid & 3, wn = wid >> 2;
    int bh = blockIdx.z, b = bh >> 3, h = bh & 7;
    size_t sq0 = (size_t)blockIdx.y * 128;
    const uint32_t* Qhb = Qh + ((size_t)b * S_ + sq0) * 256 + h * 32;
    const uint32_t* Qlb = Ql + ((size_t)b * S_ + sq0) * 256 + h * 32;

    uint4 rah[2], ral[2], rbh, rbl;
    // stage Q chunks 0 and 1 (persist across sk tiles)
    loadA_cp(Qhb, Qlb, tid, rah, ral);
    storeA_cp(rah, ral, tid, buf0);
    loadA_cp(Qhb + 16, Qlb + 16, tid, rah, ral);
    storeA_cp(rah, ral, tid, buf1);

    for (int skt = 0; skt < 4; skt++) {
        size_t sk0 = ((size_t)blockIdx.x * 4 + skt) * 64;
        const uint32_t* Khb = Kh + ((size_t)b * S_ + sk0) * 256 + h * 32;
        const uint32_t* Klb = Kl + ((size_t)b * S_ + sk0) * 256 + h * 32;
        loadB_cp(Khb, Klb, tid, rbh, rbl);
        storeB_cp(rbh, rbl, tid, buf0);
        loadB_cp(Khb + 16, Klb + 16, tid, rbh, rbl);
        storeB_cp(rbh, rbl, tid, buf1);
        __syncthreads();
        float acc[2][4][4] = {};
        compute_chunk(buf0, wm, wn, lane, acc);
        compute_chunk(buf1, wm, wn, lane, acc);
        store_f32(attn + ((size_t)bh * S_ + sq0) * S_ + sk0, S_, wm, wn, lane, acc, 0.125f);
        __syncthreads();
    }
}

// ---------------- av: oh = attn @ V ----------------
__global__ __launch_bounds__(256) void av_mma(const float* __restrict__ attn,
                                              const uint32_t* __restrict__ Vh,
                                              const uint32_t* __restrict__ Vl,
                                              float* __restrict__ oh) {
    extern __shared__ uint32_t sm[];
    uint32_t* buf0 = sm;
    uint32_t* buf1 = sm + BUF_SZ;
    int tid = threadIdx.x, lane = tid & 31, wid = tid >> 5;
    int wm = wid & 3, wn = wid >> 2;
    int bh = blockIdx.y, b = bh >> 3, h = bh & 7;
    size_t sq0 = (size_t)blockIdx.x * 128;
    const float* Pb = attn + ((size_t)bh * S_ + sq0) * S_;
    const uint32_t* Vhb = Vh + (size_t)b * S_ * 256 + h * 32;
    const uint32_t* Vlb = Vl + (size_t)b * S_ * 256 + h * 32;

    float4 rf[4];
    uint32_t rth[4], rtl[4];
    float acc[2][4][4] = {};

    loadA_sp(Pb, S_, tid, rf);
    loadBT(Vhb, Vlb, tid, rth, rtl);
    storeA_sp(rf, tid, buf0);
    storeBT(rth, rtl, tid, buf0);
    __syncthreads();

    const int NC = S_ / 32;   // 64
    for (int c = 0; c < NC; c++) {
        uint32_t* cur = (c & 1) ? buf1 : buf0;
        uint32_t* nxt = (c & 1) ? buf0 : buf1;
        if (c + 1 < NC) {
            loadA_sp(Pb + (c + 1) * 32, S_, tid, rf);
            loadBT(Vhb + (size_t)(c + 1) * 32 * 256, Vlb + (size_t)(c + 1) * 32 * 256,
                   tid, rth, rtl);
        }
        compute_chunk(cur, wm, wn, lane, acc);
        if (c + 1 < NC) {
            storeA_sp(rf, tid, nxt);
            storeBT(rth, rtl, tid, nxt);
        }
        __syncthreads();
    }
    store_f32(oh + ((size_t)b * S_ + sq0) * DM + h * 64, DM, wm, wn, lane, acc, 1.0f);
}

// ---------------- weight pre-split: W f32 [512,512] -> hi/lo u32-pair [512,256] ----------------
__global__ void wconv(const float* __restrict__ W, uint32_t* __restrict__ Hh,
                      uint32_t* __restrict__ Hl) {
    int slot = blockIdx.x * 256 + threadIdx.x;       // 131072 slots
    float2 w = *(const float2*)&W[(size_t)slot * 2];
    uint32_t hp, lp;
    split2(w.x, w.y, hp, lp);
    Hh[slot] = hp;
    Hl[slot] = lp;
}

// ---------------- LayerNorm: f32 in -> hi/lo bf16-pair out ----------------
__global__ void ln_kernel(const float* __restrict__ x, uint32_t* __restrict__ yh,
                          uint32_t* __restrict__ yl, const float* __restrict__ g,
                          const float* __restrict__ bb) {
    int row = blockIdx.x;
    int t = threadIdx.x;                       // 256 threads, 2 cols each
    float2 f = *(const float2*)&x[(size_t)row * DM + 2 * t];
    __shared__ float red[256];
    red[t] = f.x + f.y;
    __syncthreads();
    for (int o = 128; o > 0; o >>= 1) { if (t < o) red[t] += red[t + o]; __syncthreads(); }
    float mu = red[0] * (1.0f / DM);
    __syncthreads();
    float d0 = f.x - mu, d1 = f.y - mu;
    red[t] = d0 * d0 + d1 * d1;
    __syncthreads();
    for (int o = 128; o > 0; o >>= 1) { if (t < o) red[t] += red[t + o]; __syncthreads(); }
    float rstd = rsqrtf(red[0] * (1.0f / DM) + 1e-5f);
    float2 gg = *(const float2*)&g[2 * t];
    float2 bv = *(const float2*)&bb[2 * t];
    float y0 = d0 * rstd * gg.x + bv.x;
    float y1 = d1 * rstd * gg.y + bv.y;
    uint32_t hp, lp;
    split2(y0, y1, hp, lp);
    yh[(size_t)row * 256 + t] = hp;
    yl[(size_t)row * 256 + t] = lp;
}

// ---------------- softmax in place over rows of 2048 (float4) ----------------
__global__ __launch_bounds__(256) void softmax_kernel(float* __restrict__ attn) {
    size_t row = blockIdx.x;
    float4* p = (float4*)(attn + row * (size_t)S_);
    int tid = threadIdx.x;
    float4 v0 = p[tid], v1 = p[tid + 256];
    float m = fmaxf(fmaxf(fmaxf(v0.x, v0.y), fmaxf(v0.z, v0.w)),
                    fmaxf(fmaxf(v1.x, v1.y), fmaxf(v1.z, v1.w)));
    __shared__ float red[256];
    red[tid] = m;
    __syncthreads();
    for (int o = 128; o > 0; o >>= 1) { if (tid < o) red[tid] = fmaxf(red[tid], red[tid + o]); __syncthreads(); }
    m = red[0];
    __syncthreads();
    v0.x = __expf(v0.x - m); v0.y = __expf(v0.y - m); v0.z = __expf(v0.z - m); v0.w = __expf(v0.w - m);
    v1.x = __expf(v1.x - m); v1.y = __expf(v1.y - m); v1.z = __expf(v1.z - m); v1.w = __expf(v1.w - m);
    float s = v0.x + v0.y + v0.z + v0.w + v1.x + v1.y + v1.z + v1.w;
    red[tid] = s;
    __syncthreads();
    for (int o = 128; o > 0; o >>= 1) { if (tid < o) red[tid] += red[tid + o]; __syncthreads(); }
    float inv = 1.0f / red[0];
    v0.x *= inv; v0.y *= inv; v0.z *= inv; v0.w *= inv;
    v1.x *= inv; v1.y *= inv; v1.z *= inv; v1.w *= inv;
    p[tid] = v0;
    p[tid + 256] = v1;
}

extern "C" void kernel_launch(void* const* d_in, const int* in_sizes, int n_in,
                              void* d_out, int out_size) {
    const float* q    = (const float*)d_in[0];
    const float* k    = (const float*)d_in[1];
    const float* v    = (const float*)d_in[2];
    const float* W_Q  = (const float*)d_in[3];
    const float* W_K  = (const float*)d_in[4];
    const float* W_V  = (const float*)d_in[5];
    const float* W_fc = (const float*)d_in[6];
    const float* ln_g = (const float*)d_in[7];
    const float* ln_b = (const float*)d_in[8];

    float* out  = (float*)d_out;                       // [B,S,512]
    float* attn = out + (size_t)B_ * S_ * DM;          // [B,H,S,S]

    uint32_t *bh, *bl, *qh, *ql, *kh, *kl, *vh, *vl, *wh, *wl;
    float* oh;
    cudaGetSymbolAddress((void**)&bh, g_bh);  cudaGetSymbolAddress((void**)&bl, g_bl);
    cudaGetSymbolAddress((void**)&qh, g_qh);  cudaGetSymbolAddress((void**)&ql, g_ql);
    cudaGetSymbolAddress((void**)&kh, g_kh);  cudaGetSymbolAddress((void**)&kl, g_kl);
    cudaGetSymbolAddress((void**)&vh, g_vh);  cudaGetSymbolAddress((void**)&vl, g_vl);
    cudaGetSymbolAddress((void**)&wh, g_wh);  cudaGetSymbolAddress((void**)&wl, g_wl);
    cudaGetSymbolAddress((void**)&oh, g_oh);

    const int SMEM = 2 * BUF_SZ * 4;                   // 61440 B
    cudaFuncSetAttribute(proj_mma<0>, cudaFuncAttributeMaxDynamicSharedMemorySize, SMEM);
    cudaFuncSetAttribute(proj_mma<1>, cudaFuncAttributeMaxDynamicSharedMemorySize, SMEM);
    cudaFuncSetAttribute(scores_mma,  cudaFuncAttributeMaxDynamicSharedMemorySize, SMEM);
    cudaFuncSetAttribute(av_mma,      cudaFuncAttributeMaxDynamicSharedMemorySize, SMEM);

    const int ROWS = B_ * S_;                          // 8192
    dim3 proj_grid(DM / 64, ROWS / 128);               // (8, 64)

    // pre-split weights
    wconv<<<512, 256>>>(W_Q,  wh,              wl);
    wconv<<<512, 256>>>(W_K,  wh + 131072,     wl + 131072);
    wconv<<<512, 256>>>(W_V,  wh + 2 * 131072, wl + 2 * 131072);
    wconv<<<512, 256>>>(W_fc, wh + 3 * 131072, wl + 3 * 131072);

    // Q path
    ln_kernel<<<ROWS, 256>>>(q, bh, bl, ln_g, ln_b);
    proj_mma<1><<<proj_grid, 256, SMEM>>>(bh, bl, wh, wl, nullptr, qh, ql);
    // K path
    ln_kernel<<<ROWS, 256>>>(k, bh, bl, ln_g, ln_b);
    proj_mma<1><<<proj_grid, 256, SMEM>>>(bh, bl, wh + 131072, wl + 131072, nullptr, kh, kl);
    // V path
    ln_kernel<<<ROWS, 256>>>(v, bh, bl, ln_g, ln_b);
    proj_mma<1><<<proj_grid, 256, SMEM>>>(bh, bl, wh + 2 * 131072, wl + 2 * 131072, nullptr, vh, vl);

    // Attention
    scores_mma<<<dim3(8, 16, 32), 256, SMEM>>>(qh, ql, kh, kl, attn);
    softmax_kernel<<<B_ * H_ * S_, 256>>>(attn);
    av_mma<<<dim3(16, 32), 256, SMEM>>>(attn, vh, vl, oh);

    // Output LN + fc
    ln_kernel<<<ROWS, 256>>>(oh, bh, bl, ln_g, ln_b);
    proj_mma<0><<<proj_grid, 256, SMEM>>>(bh, bl, wh + 3 * 131072, wl + 3 * 131072,
                                          out, nullptr, nullptr);
}